// round 14
// baseline (speedup 1.0000x reference)
#include <cuda_runtime.h>
#include <cuda_bf16.h>
#include <cstdint>

// BoxCrop via SEPARABLE two-pass bilinear:
//  pass1: horizontal resample of each source crop row -> tmp[b][c][r][ix] (r = y - yb)
//  pass2: vertical lerp of two tmp rows (coalesced) + pad fill.
// Exactly matches reference op order: top=v00*(1-wx)+v01*wx ; val=top*(1-wy)+bot*wy.

#define O_SIZE   336
#define IMG_H    768
#define IMG_W    768
#define IMG_HW   (IMG_H * IMG_W)
#define FILL_V   127.0f
#define BATCH    64
#define MAXROWS  384          // hb < 384
#define GROUPS_X 168          // 336/2

__device__ float g_tmp[BATCH * 3 * MAXROWS * O_SIZE];   // ~99 MB static scratch

// ---------------- pass 1: horizontal ----------------
__global__ void __launch_bounds__(256) pass1_kernel(
    const float* __restrict__ images,
    const int* __restrict__ boxes)
{
    const int b  = blockIdx.z;
    const int ix = blockIdx.x * blockDim.x + threadIdx.x;   // 0..new_w-1
    const int r  = blockIdx.y * blockDim.y + threadIdx.y;   // 0..hb-1

    const int4 box = __ldg((const int4*)boxes + b);
    const int xb = box.x, yb = box.y, wb = box.z, hb = box.w;
    if (r >= hb) return;
    const float wf = (float)wb;
    const float hf = (float)hb;

    // Exact fp32 matching JAX for the discrete sizes
    const float scale = 336.0f / fmaxf(wf, hf);
    const int new_w = (int)rintf(wf * scale);
    if (ix >= new_w) return;

    const float src_x = ((float)xb - 0.5f) + __fdividef(((float)ix + 0.5f) * wf, (float)new_w);
    const float x0f = floorf(src_x);
    const float wx  = src_x - x0f;
    const int xlo = xb, xhi = xb + wb - 1;
    const int x0i = (int)x0f;
    const int x0 = min(max(x0i,     xlo), xhi);    // clamp from UNCLAMPED idx
    const int x1 = min(max(x0i + 1, xlo), xhi);

    const int row = (yb + r) * IMG_W;
    const float* img = images + (size_t)b * 3 * IMG_HW + row;
    float* t = g_tmp + ((size_t)(b * 3) * MAXROWS + r) * O_SIZE + ix;

    const float owx = 1.0f - wx;
    float v0[3], v1[3];
    #pragma unroll
    for (int c = 0; c < 3; c++) {
        v0[c] = __ldg(img + c * IMG_HW + x0);
        v1[c] = __ldg(img + c * IMG_HW + x1);
    }
    #pragma unroll
    for (int c = 0; c < 3; c++) {
        t[(size_t)c * (MAXROWS * O_SIZE)] = v0[c] * owx + v1[c] * wx;
    }
}

// ---------------- pass 2: vertical + pad ----------------
__global__ void __launch_bounds__(256) pass2_kernel(
    const int* __restrict__ boxes,
    float* __restrict__ out)
{
    const int b  = blockIdx.z;
    const int g  = blockIdx.x * blockDim.x + threadIdx.x;
    const int oy = blockIdx.y * blockDim.y + threadIdx.y;
    if (g >= GROUPS_X) return;
    const int ox0 = g * 2;

    const int4 box = __ldg((const int4*)boxes + b);
    const int xb = box.x, yb = box.y, wb = box.z, hb = box.w;
    const float wf = (float)wb;
    const float hf = (float)hb;

    const float scale = 336.0f / fmaxf(wf, hf);
    const int new_w = (int)rintf(wf * scale);
    const int new_h = (int)rintf(hf * scale);
    const int pad_top  = (hb <  wb) ? (O_SIZE - new_h) / 2 : 0;
    const int pad_left = (hb >= wb) ? (O_SIZE - new_w) / 2 : 0;

    float2* outp = (float2*)(out + ((size_t)b * 3) * (O_SIZE * O_SIZE) + oy * O_SIZE + ox0);
    const int cstride2 = (O_SIZE * O_SIZE) / 2;
    const float2 fill2 = make_float2(FILL_V, FILL_V);

    const int iy  = oy  - pad_top;
    const int ix0 = ox0 - pad_left;

    if ((unsigned)iy >= (unsigned)new_h || ix0 + 1 < 0 || ix0 >= new_w) {
        outp[0]            = fill2;
        outp[cstride2]     = fill2;
        outp[2 * cstride2] = fill2;
        return;
    }

    // y side: clamp from UNCLAMPED floor index, then shift to tmp row space
    const float src_y = ((float)yb - 0.5f) + __fdividef(((float)iy + 0.5f) * hf, (float)new_h);
    const float y0f = floorf(src_y);
    const float wy  = src_y - y0f;
    const int ylo = yb, yhi = yb + hb - 1;
    const int y0i = (int)y0f;
    const int r0 = min(max(y0i,     ylo), yhi) - yb;
    const int r1 = min(max(y0i + 1, ylo), yhi) - yb;
    const float owy = 1.0f - wy;

    // x validity + safe (clamped) tmp column for the pad lanes
    const bool va = ((unsigned)ix0       < (unsigned)new_w);
    const bool vb = ((unsigned)(ix0 + 1) < (unsigned)new_w);
    const int ja = min(max(ix0,     0), new_w - 1);
    const int jb = min(max(ix0 + 1, 0), new_w - 1);

    const float* t0 = g_tmp + ((size_t)(b * 3) * MAXROWS + r0) * O_SIZE;
    const float* t1 = g_tmp + ((size_t)(b * 3) * MAXROWS + r1) * O_SIZE;

    // batch all 12 loads (3 ch x 2 rows x 2 px), coalesced along ix
    float ta[3], tb[3], ba[3], bb[3];
    #pragma unroll
    for (int c = 0; c < 3; c++) {
        const size_t co = (size_t)c * (MAXROWS * O_SIZE);
        ta[c] = __ldg(t0 + co + ja);
        tb[c] = __ldg(t0 + co + jb);
        ba[c] = __ldg(t1 + co + ja);
        bb[c] = __ldg(t1 + co + jb);
    }

    #pragma unroll
    for (int c = 0; c < 3; c++) {
        const float va_f = ta[c] * owy + ba[c] * wy;
        const float vb_f = tb[c] * owy + bb[c] * wy;
        float2 o;
        o.x = va ? va_f : FILL_V;
        o.y = vb ? vb_f : FILL_V;
        outp[c * cstride2] = o;
    }
}

extern "C" void kernel_launch(void* const* d_in, const int* in_sizes, int n_in,
                              void* d_out, int out_size)
{
    const float* images = (const float*)d_in[0];
    const int*   boxes  = (const int*)d_in[1];
    float*       out    = (float*)d_out;

    {   // pass 1: x covers up to 336 resampled cols, y covers up to 384 source rows
        dim3 block(64, 4, 1);
        dim3 grid((O_SIZE + 63) / 64, (MAXROWS + 3) / 4, BATCH);   // 6 x 96 x 64
        pass1_kernel<<<grid, block>>>(images, boxes);
    }
    {   // pass 2
        dim3 block(32, 8, 1);
        dim3 grid((GROUPS_X + 31) / 32, O_SIZE / 8, BATCH);        // 6 x 42 x 64
        pass2_kernel<<<grid, block>>>(boxes, out);
    }
}

// round 15
// speedup vs baseline: 1.7172x; 1.7172x over previous
#include <cuda_runtime.h>
#include <cuda_bf16.h>
#include <cstdint>

// BoxCrop: crop -> aspect-preserving bilinear resize (long side = 336) -> pad(127)
// images: [64, 3, 768, 768] f32, boxes: [64, 4] i32 (XYWH), out: [64, 3, 336, 336] f32
// 2x2 output quad per thread. Since resize step <= 383/336 ~ 1.14, adjacent output
// rows usually share a source row (warp-uniform test) -> 3-row fast path cuts
// gather LDG count from 16 to 12 per channel-quad.

#define O_SIZE   336
#define HW_O     (O_SIZE * O_SIZE)
#define IMG_W    768
#define IMG_HW   (768 * 768)
#define FILL_V   127.0f
#define GROUPS   168         // 336 / 2

__global__ void __launch_bounds__(256) boxcrop_kernel(
    const float* __restrict__ images,
    const int* __restrict__ boxes,
    float* __restrict__ out)
{
    const int b  = blockIdx.z;
    const int gx = blockIdx.x * 32 + threadIdx.x;
    const int gy = blockIdx.y * 8 + threadIdx.y;
    if (gx >= GROUPS) return;
    const int ox0 = gx * 2;
    const int oy0 = gy * 2;

    const int4 box = __ldg((const int4*)boxes + b);
    const int xb = box.x, yb = box.y, wb = box.z, hb = box.w;
    const float wf = (float)wb;
    const float hf = (float)hb;

    // Exact fp32 matching JAX: scale = 336/max; round-half-even via rintf
    const float scale = 336.0f / fmaxf(wf, hf);
    const int new_w = (int)rintf(wf * scale);
    const int new_h = (int)rintf(hf * scale);
    const int pad_top  = (hb <  wb) ? (O_SIZE - new_h) / 2 : 0;
    const int pad_left = (hb >= wb) ? (O_SIZE - new_w) / 2 : 0;

    const int iyA = oy0 - pad_top,  iyB = iyA + 1;
    const int ixA = ox0 - pad_left, ixB = ixA + 1;
    const bool vyA = (unsigned)iyA < (unsigned)new_h;
    const bool vyB = (unsigned)iyB < (unsigned)new_h;
    const bool vxA = (unsigned)ixA < (unsigned)new_w;
    const bool vxB = (unsigned)ixB < (unsigned)new_w;

    float* ob = out + ((size_t)b * 3) * HW_O + oy0 * O_SIZE + ox0;
    const float2 fill2 = make_float2(FILL_V, FILL_V);

    if (!((vyA | vyB) && (vxA | vxB))) {
        #pragma unroll
        for (int c = 0; c < 3; c++) {
            *(float2*)(ob + c * HW_O)          = fill2;
            *(float2*)(ob + c * HW_O + O_SIZE) = fill2;
        }
        return;
    }

    // ---- clamped-safe output coords for sampling (invalid lanes -> FILL later) ----
    const int iyAs = min(max(iyA, 0), new_h - 1);
    const int iyBs = min(max(iyB, 0), new_h - 1);
    const int ixAs = min(max(ixA, 0), new_w - 1);
    const int ixBs = min(max(ixB, 0), new_w - 1);

    const int ylo = yb, yhi = yb + hb - 1;
    const int xlo = xb, xhi = xb + wb - 1;
    const float ybm = (float)yb - 0.5f, xbm = (float)xb - 0.5f;
    const float inv_nh = (float)new_h, inv_nw = (float)new_w;

    // ---- y side: two rows (clamp from UNCLAMPED floor index — JAX semantics) ----
    const float syA = ybm + __fdividef(((float)iyAs + 0.5f) * hf, inv_nh);
    const float yA0f = floorf(syA);
    const float wyA  = syA - yA0f;
    const int yA0i = (int)yA0f;
    const int yA0 = min(max(yA0i,     ylo), yhi);
    const int yA1 = min(max(yA0i + 1, ylo), yhi);

    const float syB = ybm + __fdividef(((float)iyBs + 0.5f) * hf, inv_nh);
    const float yB0f = floorf(syB);
    const float wyB  = syB - yB0f;
    const int yB0i = (int)yB0f;
    const int yB0 = min(max(yB0i,     ylo), yhi);
    const int yB1 = min(max(yB0i + 1, ylo), yhi);

    const float owyA = 1.0f - wyA, owyB = 1.0f - wyB;

    // ---- x side: two pixels ----
    const float sxA = xbm + __fdividef(((float)ixAs + 0.5f) * wf, inv_nw);
    const float xA0f = floorf(sxA);
    const float wxA  = sxA - xA0f;
    const int xA0i = (int)xA0f;
    const int x0a = min(max(xA0i,     xlo), xhi);
    const int x1a = min(max(xA0i + 1, xlo), xhi);

    const float sxB = xbm + __fdividef(((float)ixBs + 0.5f) * wf, inv_nw);
    const float xB0f = floorf(sxB);
    const float wxB  = sxB - xB0f;
    const int xB0i = (int)xB0f;
    const int x0b = min(max(xB0i,     xlo), xhi);
    const int x1b = min(max(xB0i + 1, xlo), xhi);

    const float owxA = 1.0f - wxA, owxB = 1.0f - wxB;

    const float* img = images + (size_t)b * 3 * IMG_HW;

    const int rA0 = yA0 * IMG_W;
    const int rA1 = yA1 * IMG_W;
    const int rB0 = yB0 * IMG_W;
    const int rB1 = yB1 * IMG_W;

    float vAA[3], vAB[3], vBA[3], vBB[3];   // [ch] results: row(A/B) x px(A/B)

    if (yA1 == yB0) {
        // ---- FAST PATH (warp-uniform): rows {rA0, rA1==rB0, rB1} -> 12 LDG/ch-quad ----
        #pragma unroll
        for (int c = 0; c < 3; c++) {
            const float* p = img + c * IMG_HW;
            const float a0 = __ldg(p + rA0 + x0a);
            const float a1 = __ldg(p + rA0 + x1a);
            const float a2 = __ldg(p + rA0 + x0b);
            const float a3 = __ldg(p + rA0 + x1b);
            const float m0 = __ldg(p + rA1 + x0a);
            const float m1 = __ldg(p + rA1 + x1a);
            const float m2 = __ldg(p + rA1 + x0b);
            const float m3 = __ldg(p + rA1 + x1b);
            const float c0 = __ldg(p + rB1 + x0a);
            const float c1 = __ldg(p + rB1 + x1a);
            const float c2 = __ldg(p + rB1 + x0b);
            const float c3 = __ldg(p + rB1 + x1b);

            const float topA_a = a0 * owxA + a1 * wxA;
            const float midA_a = m0 * owxA + m1 * wxA;
            const float botA_a = c0 * owxA + c1 * wxA;
            const float topA_b = a2 * owxB + a3 * wxB;
            const float midA_b = m2 * owxB + m3 * wxB;
            const float botA_b = c2 * owxB + c3 * wxB;

            vAA[c] = topA_a * owyA + midA_a * wyA;   // row oy0,   px A
            vAB[c] = topA_b * owyA + midA_b * wyA;   // row oy0,   px B
            vBA[c] = midA_a * owyB + botA_a * wyB;   // row oy0+1, px A (mid row reused)
            vBB[c] = midA_b * owyB + botA_b * wyB;
        }
    } else {
        // ---- SLOW PATH: 4 distinct rows -> 16 LDG/ch-quad ----
        #pragma unroll
        for (int c = 0; c < 3; c++) {
            const float* p = img + c * IMG_HW;
            const float a0 = __ldg(p + rA0 + x0a);
            const float a1 = __ldg(p + rA0 + x1a);
            const float a2 = __ldg(p + rA0 + x0b);
            const float a3 = __ldg(p + rA0 + x1b);
            const float d0 = __ldg(p + rA1 + x0a);
            const float d1 = __ldg(p + rA1 + x1a);
            const float d2 = __ldg(p + rA1 + x0b);
            const float d3 = __ldg(p + rA1 + x1b);
            const float e0 = __ldg(p + rB0 + x0a);
            const float e1 = __ldg(p + rB0 + x1a);
            const float e2 = __ldg(p + rB0 + x0b);
            const float e3 = __ldg(p + rB0 + x1b);
            const float f0 = __ldg(p + rB1 + x0a);
            const float f1 = __ldg(p + rB1 + x1a);
            const float f2 = __ldg(p + rB1 + x0b);
            const float f3 = __ldg(p + rB1 + x1b);

            const float tA_a = a0 * owxA + a1 * wxA;
            const float bA_a = d0 * owxA + d1 * wxA;
            const float tA_b = a2 * owxB + a3 * wxB;
            const float bA_b = d2 * owxB + d3 * wxB;
            const float tB_a = e0 * owxA + e1 * wxA;
            const float bB_a = f0 * owxA + f1 * wxA;
            const float tB_b = e2 * owxB + e3 * wxB;
            const float bB_b = f2 * owxB + f3 * wxB;

            vAA[c] = tA_a * owyA + bA_a * wyA;
            vAB[c] = tA_b * owyA + bA_b * wyA;
            vBA[c] = tB_a * owyB + bB_a * wyB;
            vBB[c] = tB_b * owyB + bB_b * wyB;
        }
    }

    const bool vAAp = vyA & vxA, vABp = vyA & vxB;
    const bool vBAp = vyB & vxA, vBBp = vyB & vxB;

    #pragma unroll
    for (int c = 0; c < 3; c++) {
        float2 oA, oB;
        oA.x = vAAp ? vAA[c] : FILL_V;
        oA.y = vABp ? vAB[c] : FILL_V;
        oB.x = vBAp ? vBA[c] : FILL_V;
        oB.y = vBBp ? vBB[c] : FILL_V;
        *(float2*)(ob + c * HW_O)          = oA;
        *(float2*)(ob + c * HW_O + O_SIZE) = oB;
    }
}

extern "C" void kernel_launch(void* const* d_in, const int* in_sizes, int n_in,
                              void* d_out, int out_size)
{
    const float* images = (const float*)d_in[0];
    const int*   boxes  = (const int*)d_in[1];
    float*       out    = (float*)d_out;

    dim3 block(32, 8, 1);
    dim3 grid((GROUPS + 31) / 32, GROUPS / 8, 64);   // 6 x 21 x 64
    boxcrop_kernel<<<grid, block>>>(images, boxes, out);
}

// round 16
// speedup vs baseline: 1.7295x; 1.0072x over previous
#include <cuda_runtime.h>
#include <cuda_bf16.h>
#include <cstdint>

// BoxCrop: crop -> aspect-preserving bilinear resize (long side = 336) -> pad(127)
// images: [64, 3, 768, 768] f32, boxes: [64, 4] i32 (XYWH), out: [64, 3, 336, 336] f32
// 2x2 output quad per thread; shared-middle-row fast path (12 LDG/ch-quad);
// per-channel immediate stores to shorten live ranges; 5 blocks/SM for occupancy.

#define O_SIZE   336
#define HW_O     (O_SIZE * O_SIZE)
#define IMG_W    768
#define IMG_HW   (768 * 768)
#define FILL_V   127.0f
#define GROUPS   168         // 336 / 2

__global__ void __launch_bounds__(256, 5) boxcrop_kernel(
    const float* __restrict__ images,
    const int* __restrict__ boxes,
    float* __restrict__ out)
{
    const int b  = blockIdx.z;
    const int gx = blockIdx.x * 32 + threadIdx.x;
    const int gy = blockIdx.y * 8 + threadIdx.y;
    if (gx >= GROUPS) return;
    const int ox0 = gx * 2;
    const int oy0 = gy * 2;

    const int4 box = __ldg((const int4*)boxes + b);
    const int xb = box.x, yb = box.y, wb = box.z, hb = box.w;
    const float wf = (float)wb;
    const float hf = (float)hb;

    // Exact fp32 matching JAX: scale = 336/max; round-half-even via rintf
    const float scale = 336.0f / fmaxf(wf, hf);
    const int new_w = (int)rintf(wf * scale);
    const int new_h = (int)rintf(hf * scale);
    const int pad_top  = (hb <  wb) ? (O_SIZE - new_h) / 2 : 0;
    const int pad_left = (hb >= wb) ? (O_SIZE - new_w) / 2 : 0;

    const int iyA = oy0 - pad_top,  iyB = iyA + 1;
    const int ixA = ox0 - pad_left, ixB = ixA + 1;
    const bool vyA = (unsigned)iyA < (unsigned)new_h;
    const bool vyB = (unsigned)iyB < (unsigned)new_h;
    const bool vxA = (unsigned)ixA < (unsigned)new_w;
    const bool vxB = (unsigned)ixB < (unsigned)new_w;

    float* ob = out + ((size_t)b * 3) * HW_O + oy0 * O_SIZE + ox0;
    const float2 fill2 = make_float2(FILL_V, FILL_V);

    if (!((vyA | vyB) && (vxA | vxB))) {
        #pragma unroll
        for (int c = 0; c < 3; c++) {
            *(float2*)(ob + c * HW_O)          = fill2;
            *(float2*)(ob + c * HW_O + O_SIZE) = fill2;
        }
        return;
    }

    // ---- clamped-safe output coords for sampling (invalid lanes -> FILL later) ----
    const int iyAs = min(max(iyA, 0), new_h - 1);
    const int iyBs = min(max(iyB, 0), new_h - 1);
    const int ixAs = min(max(ixA, 0), new_w - 1);
    const int ixBs = min(max(ixB, 0), new_w - 1);

    const int ylo = yb, yhi = yb + hb - 1;
    const int xlo = xb, xhi = xb + wb - 1;
    const float ybm = (float)yb - 0.5f, xbm = (float)xb - 0.5f;
    const float nhf = (float)new_h, nwf = (float)new_w;

    // ---- y side: two rows (clamp from UNCLAMPED floor index — JAX semantics) ----
    const float syA = ybm + __fdividef(((float)iyAs + 0.5f) * hf, nhf);
    const float yA0f = floorf(syA);
    const float wyA  = syA - yA0f;
    const int yA0i = (int)yA0f;
    const int yA0 = min(max(yA0i,     ylo), yhi);
    const int yA1 = min(max(yA0i + 1, ylo), yhi);

    const float syB = ybm + __fdividef(((float)iyBs + 0.5f) * hf, nhf);
    const float yB0f = floorf(syB);
    const float wyB  = syB - yB0f;
    const int yB0i = (int)yB0f;
    const int yB0 = min(max(yB0i,     ylo), yhi);
    const int yB1 = min(max(yB0i + 1, ylo), yhi);

    const float owyA = 1.0f - wyA, owyB = 1.0f - wyB;

    // ---- x side: two pixels ----
    const float sxA = xbm + __fdividef(((float)ixAs + 0.5f) * wf, nwf);
    const float xA0f = floorf(sxA);
    const float wxA  = sxA - xA0f;
    const int xA0i = (int)xA0f;
    const int x0a = min(max(xA0i,     xlo), xhi);
    const int x1a = min(max(xA0i + 1, xlo), xhi);

    const float sxB = xbm + __fdividef(((float)ixBs + 0.5f) * wf, nwf);
    const float xB0f = floorf(sxB);
    const float wxB  = sxB - xB0f;
    const int xB0i = (int)xB0f;
    const int x0b = min(max(xB0i,     xlo), xhi);
    const int x1b = min(max(xB0i + 1, xlo), xhi);

    const float owxA = 1.0f - wxA, owxB = 1.0f - wxB;

    const float* img = images + (size_t)b * 3 * IMG_HW;

    const int rA0 = yA0 * IMG_W;
    const int rA1 = yA1 * IMG_W;
    const int rB0 = yB0 * IMG_W;
    const int rB1 = yB1 * IMG_W;

    const bool vAAp = vyA & vxA, vABp = vyA & vxB;
    const bool vBAp = vyB & vxA, vBBp = vyB & vxB;

    if (yA1 == yB0) {
        // ---- FAST PATH (warp-uniform): rows {rA0, rA1==rB0, rB1}: 12 LDG/ch-quad ----
        #pragma unroll
        for (int c = 0; c < 3; c++) {
            const float* p = img + c * IMG_HW;
            const float a0 = __ldg(p + rA0 + x0a);
            const float a1 = __ldg(p + rA0 + x1a);
            const float a2 = __ldg(p + rA0 + x0b);
            const float a3 = __ldg(p + rA0 + x1b);
            const float m0 = __ldg(p + rA1 + x0a);
            const float m1 = __ldg(p + rA1 + x1a);
            const float m2 = __ldg(p + rA1 + x0b);
            const float m3 = __ldg(p + rA1 + x1b);
            const float c0 = __ldg(p + rB1 + x0a);
            const float c1 = __ldg(p + rB1 + x1a);
            const float c2 = __ldg(p + rB1 + x0b);
            const float c3 = __ldg(p + rB1 + x1b);

            const float top_a = a0 * owxA + a1 * wxA;
            const float mid_a = m0 * owxA + m1 * wxA;
            const float bot_a = c0 * owxA + c1 * wxA;
            const float top_b = a2 * owxB + a3 * wxB;
            const float mid_b = m2 * owxB + m3 * wxB;
            const float bot_b = c2 * owxB + c3 * wxB;

            float2 oA, oB;
            oA.x = vAAp ? (top_a * owyA + mid_a * wyA) : FILL_V;
            oA.y = vABp ? (top_b * owyA + mid_b * wyA) : FILL_V;
            oB.x = vBAp ? (mid_a * owyB + bot_a * wyB) : FILL_V;
            oB.y = vBBp ? (mid_b * owyB + bot_b * wyB) : FILL_V;
            *(float2*)(ob + c * HW_O)          = oA;
            *(float2*)(ob + c * HW_O + O_SIZE) = oB;
        }
    } else {
        // ---- SLOW PATH: 4 distinct rows: 16 LDG/ch-quad ----
        #pragma unroll
        for (int c = 0; c < 3; c++) {
            const float* p = img + c * IMG_HW;
            const float a0 = __ldg(p + rA0 + x0a);
            const float a1 = __ldg(p + rA0 + x1a);
            const float a2 = __ldg(p + rA0 + x0b);
            const float a3 = __ldg(p + rA0 + x1b);
            const float d0 = __ldg(p + rA1 + x0a);
            const float d1 = __ldg(p + rA1 + x1a);
            const float d2 = __ldg(p + rA1 + x0b);
            const float d3 = __ldg(p + rA1 + x1b);
            const float e0 = __ldg(p + rB0 + x0a);
            const float e1 = __ldg(p + rB0 + x1a);
            const float e2 = __ldg(p + rB0 + x0b);
            const float e3 = __ldg(p + rB0 + x1b);
            const float f0 = __ldg(p + rB1 + x0a);
            const float f1 = __ldg(p + rB1 + x1a);
            const float f2 = __ldg(p + rB1 + x0b);
            const float f3 = __ldg(p + rB1 + x1b);

            const float tA_a = a0 * owxA + a1 * wxA;
            const float bA_a = d0 * owxA + d1 * wxA;
            const float tA_b = a2 * owxB + a3 * wxB;
            const float bA_b = d2 * owxB + d3 * wxB;
            const float tB_a = e0 * owxA + e1 * wxA;
            const float bB_a = f0 * owxA + f1 * wxA;
            const float tB_b = e2 * owxB + e3 * wxB;
            const float bB_b = f2 * owxB + f3 * wxB;

            float2 oA, oB;
            oA.x = vAAp ? (tA_a * owyA + bA_a * wyA) : FILL_V;
            oA.y = vABp ? (tA_b * owyA + bA_b * wyA) : FILL_V;
            oB.x = vBAp ? (tB_a * owyB + bB_a * wyB) : FILL_V;
            oB.y = vBBp ? (tB_b * owyB + bB_b * wyB) : FILL_V;
            *(float2*)(ob + c * HW_O)          = oA;
            *(float2*)(ob + c * HW_O + O_SIZE) = oB;
        }
    }
}

extern "C" void kernel_launch(void* const* d_in, const int* in_sizes, int n_in,
                              void* d_out, int out_size)
{
    const float* images = (const float*)d_in[0];
    const int*   boxes  = (const int*)d_in[1];
    float*       out    = (float*)d_out;

    dim3 block(32, 8, 1);
    dim3 grid((GROUPS + 31) / 32, GROUPS / 8, 64);   // 6 x 21 x 64
    boxcrop_kernel<<<grid, block>>>(images, boxes, out);
}